// round 2
// baseline (speedup 1.0000x reference)
#include <cuda_runtime.h>

// Effective weights: w_eff_m[u] = sum_v W_lin_m[u,v] * W_tp_m[v], pre-scaled.
// s0 = lin_norm*alpha = 1/(16*sqrt(768))
// s1 = s0/sqrt(3) = 1/768
// s2 = s0/sqrt(5)
__device__ float g_w[3 * 256];

#define S0 0.0022552744890219763f
#define S1 0.0013020833333333333f
#define S2 0.0010085837883053976f

__global__ void prep_weights_kernel(const float* __restrict__ W0,
                                    const float* __restrict__ W1,
                                    const float* __restrict__ W2,
                                    const float* __restrict__ T0,
                                    const float* __restrict__ T1,
                                    const float* __restrict__ T2) {
    // grid = 12 blocks x 256 threads. block b: matrix m = b/4, u-range = (b%4)*64 .. +64
    int b = blockIdx.x;
    int m = b >> 2;
    int ubase = (b & 3) * 64;
    const float* W = (m == 0) ? W0 : (m == 1) ? W1 : W2;
    const float* T = (m == 0) ? T0 : (m == 1) ? T1 : T2;
    float scale = (m == 0) ? S0 : (m == 1) ? S1 : S2;

    int warp = threadIdx.x >> 5;
    int lane = threadIdx.x & 31;

    float tw[8];
#pragma unroll
    for (int k = 0; k < 8; k++) tw[k] = T[lane + 32 * k];

#pragma unroll
    for (int r = 0; r < 8; r++) {
        int u = ubase + warp * 8 + r;
        const float* row = W + (size_t)u * 256;
        float acc = 0.f;
#pragma unroll
        for (int k = 0; k < 8; k++) acc += row[lane + 32 * k] * tw[k];
#pragma unroll
        for (int off = 16; off; off >>= 1)
            acc += __shfl_xor_sync(0xffffffffu, acc, off);
        if (lane == 0) g_w[m * 256 + u] = acc * scale;
    }
}

// One block (256 threads) processes nodes in a grid-stride loop.
// Per node: stage the 2304-float row in SMEM via coalesced float4 loads,
// then each thread t handles u=t for all three irreps:
//   x0[t] (stride 1), x1[t][0..2] (stride 3, conflict-free), x2[t][0..4] (stride 5, conflict-free)
__global__ void __launch_bounds__(256, 8)
energy_kernel(const float* __restrict__ nf,
              const float* __restrict__ ch,
              float* __restrict__ out, int n) {
    __shared__ float4 srow4[576];   // 2304 floats = 9216 B
    __shared__ float spart[8];
    float* srow = (float*)srow4;

    int t = threadIdx.x;
    int warp = t >> 5;
    int lane = t & 31;

    float w0 = g_w[t];
    float w1 = g_w[256 + t];
    float w2 = g_w[512 + t];

    for (int z = blockIdx.x; z < n; z += gridDim.x) {
        const float4* src = (const float4*)(nf + (size_t)z * 2304);
        float4 a = src[t];
        float4 b = src[256 + t];
        float4 cxt;
        bool extra = (t < 64);
        if (extra) cxt = src[512 + t];

        const float* cp = ch + (size_t)z * 9;
        float c0  = __ldg(cp + 0);
        float c1x = __ldg(cp + 1), c1y = __ldg(cp + 2), c1z = __ldg(cp + 3);
        float c20 = __ldg(cp + 4), c21 = __ldg(cp + 5), c22 = __ldg(cp + 6);
        float c23 = __ldg(cp + 7), c24 = __ldg(cp + 8);

        srow4[t] = a;
        srow4[256 + t] = b;
        if (extra) srow4[512 + t] = cxt;
        __syncthreads();

        float acc = w0 * srow[t] * c0;
        const float* p1 = srow + 256 + 3 * t;
        acc += w1 * (p1[0] * c1x + p1[1] * c1y + p1[2] * c1z);
        const float* p2 = srow + 1024 + 5 * t;
        acc += w2 * (p2[0] * c20 + p2[1] * c21 + p2[2] * c22 +
                     p2[3] * c23 + p2[4] * c24);

#pragma unroll
        for (int off = 16; off; off >>= 1)
            acc += __shfl_xor_sync(0xffffffffu, acc, off);
        if (lane == 0) spart[warp] = acc;
        __syncthreads();

        if (warp == 0) {
            float r = (lane < 8) ? spart[lane] : 0.f;
#pragma unroll
            for (int off = 4; off; off >>= 1)
                r += __shfl_xor_sync(0xffffffffu, r, off);
            if (lane == 0) out[z] = r;
        }
        // No extra barrier needed: next iteration's first __syncthreads()
        // orders the new row stores against this iteration's reads, and
        // spart is only rewritten after that barrier.
    }
}

extern "C" void kernel_launch(void* const* d_in, const int* in_sizes, int n_in,
                              void* d_out, int out_size) {
    const float* node_feats = (const float*)d_in[0];
    const float* charges    = (const float*)d_in[1];
    const float* W_lin0     = (const float*)d_in[2];
    const float* W_lin1     = (const float*)d_in[3];
    const float* W_lin2     = (const float*)d_in[4];
    const float* W_tp0      = (const float*)d_in[5];
    const float* W_tp1      = (const float*)d_in[6];
    const float* W_tp2      = (const float*)d_in[7];
    float* out = (float*)d_out;

    int n = in_sizes[1] / 9;   // number of nodes

    prep_weights_kernel<<<12, 256>>>(W_lin0, W_lin1, W_lin2, W_tp0, W_tp1, W_tp2);

    int grid = 2048;
    if (grid > n) grid = n;
    energy_kernel<<<grid, 256>>>(node_feats, charges, out, n);
}

// round 3
// speedup vs baseline: 1.0347x; 1.0347x over previous
#include <cuda_runtime.h>

// Effective weights: w_eff_m[u] = sum_v W_lin_m[u,v] * W_tp_m[v], pre-scaled.
// s0 = lin_norm*alpha = 1/(16*sqrt(768)); s1 = s0/sqrt(3); s2 = s0/sqrt(5)
__device__ float g_w[3 * 256];

#define S0 0.0022552744890219763f
#define S1 0.0013020833333333333f
#define S2 0.0010085837883053976f

__global__ void prep_weights_kernel(const float* __restrict__ W0,
                                    const float* __restrict__ W1,
                                    const float* __restrict__ W2,
                                    const float* __restrict__ T0,
                                    const float* __restrict__ T1,
                                    const float* __restrict__ T2) {
    int b = blockIdx.x;
    int m = b >> 2;
    int ubase = (b & 3) * 64;
    const float* W = (m == 0) ? W0 : (m == 1) ? W1 : W2;
    const float* T = (m == 0) ? T0 : (m == 1) ? T1 : T2;
    float scale = (m == 0) ? S0 : (m == 1) ? S1 : S2;

    int warp = threadIdx.x >> 5;
    int lane = threadIdx.x & 31;

    float tw[8];
#pragma unroll
    for (int k = 0; k < 8; k++) tw[k] = T[lane + 32 * k];

#pragma unroll
    for (int r = 0; r < 8; r++) {
        int u = ubase + warp * 8 + r;
        const float* row = W + (size_t)u * 256;
        float acc = 0.f;
#pragma unroll
        for (int k = 0; k < 8; k++) acc += row[lane + 32 * k] * tw[k];
#pragma unroll
        for (int off = 16; off; off >>= 1)
            acc += __shfl_xor_sync(0xffffffffu, acc, off);
        if (lane == 0) g_w[m * 256 + u] = acc * scale;
    }
}

// Block handles a contiguous chunk of 32 nodes. Charges (288 floats) staged in
// SMEM once. Per iteration: 2 nodes, coalesced float4 loads of the rows direct
// to registers, per-element weight (register) * charge (SMEM select, bank-
// conflict-free) folded in, one block reduction with a ping-pong partial
// buffer => 1 barrier per 2 nodes.
__global__ void __launch_bounds__(256, 4)
energy_kernel(const float* __restrict__ nf,
              const float* __restrict__ ch,
              float* __restrict__ out, int n) {
    __shared__ float cbuf[32 * 9];
    __shared__ float spart[2][16];

    int blockBase = blockIdx.x * 32;
    if (blockBase >= n) return;

    int t = threadIdx.x;
    int warp = t >> 5;
    int lane = t & 31;

    // Per-thread element metadata (fixed for the whole kernel):
    // slot A: float4 q = t        -> elements j = 4t+e           (x0 if t<64, else x1)
    // slot B: float4 q = t + 256  -> elements j = 1024 + 4t + e  (x2)
    // slot C: float4 q = t + 512  -> elements j = 2048 + 4t + e  (x2, t<64 only)
    float aA[4], aB[4], aC[4];
    int kA[4], kB[4], kC[4];
#pragma unroll
    for (int e = 0; e < 4; e++) {
        int jA = 4 * t + e;
        if (jA < 256) { aA[e] = g_w[jA]; kA[e] = 0; }
        else { int r = jA - 256; aA[e] = g_w[256 + r / 3]; kA[e] = 1 + r % 3; }
        int rB = 4 * t + e;                 // j = 1024 + rB
        aB[e] = g_w[512 + rB / 5]; kB[e] = 4 + rB % 5;
        int rC = 1024 + 4 * t + e;          // j = 2048 + 4t + e (t<64 only)
        if (t < 64) { aC[e] = g_w[512 + rC / 5]; kC[e] = 4 + rC % 5; }
        else        { aC[e] = 0.f; kC[e] = 0; }
    }

    // Stage all charges for this block's 32 nodes (once).
    {
        long gbase = (long)blockBase * 9;
        long lim = (long)n * 9;
        if (gbase + t < lim) cbuf[t] = __ldg(ch + gbase + t);
        if (t < 32 && gbase + 256 + t < lim) cbuf[256 + t] = __ldg(ch + gbase + 256 + t);
    }
    __syncthreads();

    int m = n - blockBase; if (m > 32) m = 32;
    int ngrp = (m + 1) >> 1;

    for (int it = 0; it < ngrp; it++) {
        int z0 = blockBase + 2 * it;
        bool v1 = (2 * it + 1) < m;

        const float4* p0 = (const float4*)(nf + (size_t)z0 * 2304);
        const float4* p1 = p0 + 576;

        float4 A0 = p0[t], B0 = p0[256 + t];
        float4 C0 = make_float4(0.f, 0.f, 0.f, 0.f);
        float4 A1 = C0, B1 = C0, C1 = C0;
        if (t < 64) C0 = p0[512 + t];
        if (v1) {
            A1 = p1[t]; B1 = p1[256 + t];
            if (t < 64) C1 = p1[512 + t];
        }

        const float* cb0 = cbuf + 18 * it;
        const float* cb1 = cb0 + 9;

        float acc0, acc1;
        if (t < 64) {
            // x0: all four elements use c0 -> one select, one mul
            acc0 = cb0[0] * (A0.x * aA[0] + A0.y * aA[1] + A0.z * aA[2] + A0.w * aA[3]);
            acc1 = cb1[0] * (A1.x * aA[0] + A1.y * aA[1] + A1.z * aA[2] + A1.w * aA[3]);
#pragma unroll
            for (int e = 0; e < 4; e++) {
                acc0 = fmaf((&C0.x)[e], aC[e] * cb0[kC[e]], acc0);
                acc1 = fmaf((&C1.x)[e], aC[e] * cb1[kC[e]], acc1);
            }
        } else {
            acc0 = 0.f; acc1 = 0.f;
#pragma unroll
            for (int e = 0; e < 4; e++) {
                acc0 = fmaf((&A0.x)[e], aA[e] * cb0[kA[e]], acc0);
                acc1 = fmaf((&A1.x)[e], aA[e] * cb1[kA[e]], acc1);
            }
        }
#pragma unroll
        for (int e = 0; e < 4; e++) {
            acc0 = fmaf((&B0.x)[e], aB[e] * cb0[kB[e]], acc0);
            acc1 = fmaf((&B1.x)[e], aB[e] * cb1[kB[e]], acc1);
        }

#pragma unroll
        for (int off = 16; off; off >>= 1) {
            acc0 += __shfl_xor_sync(0xffffffffu, acc0, off);
            acc1 += __shfl_xor_sync(0xffffffffu, acc1, off);
        }

        int buf = it & 1;
        if (lane == 0) {
            spart[buf][warp]     = acc0;
            spart[buf][8 + warp] = acc1;
        }
        __syncthreads();

        if (warp == 0) {
            float r = (lane < 16) ? spart[buf][lane] : 0.f;
            r += __shfl_xor_sync(0xffffffffu, r, 4);
            r += __shfl_xor_sync(0xffffffffu, r, 2);
            r += __shfl_xor_sync(0xffffffffu, r, 1);
            if ((lane & 7) == 0 && lane < 16) {
                int z = z0 + (lane >> 3);
                if (z - blockBase < m) out[z] = r;
            }
        }
        // Ping-pong spart: warp 0's reads of buf complete before it arrives at
        // the NEXT iteration's __syncthreads, and the same buf is rewritten
        // only after that barrier (it+2). cbuf is read-only after the initial
        // barrier.
    }
}

extern "C" void kernel_launch(void* const* d_in, const int* in_sizes, int n_in,
                              void* d_out, int out_size) {
    const float* node_feats = (const float*)d_in[0];
    const float* charges    = (const float*)d_in[1];
    const float* W_lin0     = (const float*)d_in[2];
    const float* W_lin1     = (const float*)d_in[3];
    const float* W_lin2     = (const float*)d_in[4];
    const float* W_tp0      = (const float*)d_in[5];
    const float* W_tp1      = (const float*)d_in[6];
    const float* W_tp2      = (const float*)d_in[7];
    float* out = (float*)d_out;

    int n = in_sizes[1] / 9;   // number of nodes

    prep_weights_kernel<<<12, 256>>>(W_lin0, W_lin1, W_lin2, W_tp0, W_tp1, W_tp2);

    int grid = (n + 31) / 32;
    energy_kernel<<<grid, 256>>>(node_feats, charges, out, n);
}

// round 4
// speedup vs baseline: 1.1396x; 1.1013x over previous
#include <cuda_runtime.h>

// Effective weights: w_eff_m[u] = sum_v W_lin_m[u,v] * W_tp_m[v], pre-scaled.
// s0 = lin_norm*alpha = 1/(16*sqrt(768)); s1 = s0/sqrt(3); s2 = s0/sqrt(5)
__device__ float g_w[3 * 256];

#define S0 0.0022552744890219763f
#define S1 0.0013020833333333333f
#define S2 0.0010085837883053976f

__global__ void prep_weights_kernel(const float* __restrict__ W0,
                                    const float* __restrict__ W1,
                                    const float* __restrict__ W2,
                                    const float* __restrict__ T0,
                                    const float* __restrict__ T1,
                                    const float* __restrict__ T2) {
    int b = blockIdx.x;
    int m = b >> 2;
    int ubase = (b & 3) * 64;
    const float* W = (m == 0) ? W0 : (m == 1) ? W1 : W2;
    const float* T = (m == 0) ? T0 : (m == 1) ? T1 : T2;
    float scale = (m == 0) ? S0 : (m == 1) ? S1 : S2;

    int warp = threadIdx.x >> 5;
    int lane = threadIdx.x & 31;

    float tw[8];
#pragma unroll
    for (int k = 0; k < 8; k++) tw[k] = T[lane + 32 * k];

#pragma unroll
    for (int r = 0; r < 8; r++) {
        int u = ubase + warp * 8 + r;
        const float* row = W + (size_t)u * 256;
        float acc = 0.f;
#pragma unroll
        for (int k = 0; k < 8; k++) acc += row[lane + 32 * k] * tw[k];
#pragma unroll
        for (int off = 16; off; off >>= 1)
            acc += __shfl_xor_sync(0xffffffffu, acc, off);
        if (lane == 0) g_w[m * 256 + u] = acc * scale;
    }
}

__global__ void zero_out_kernel(float* __restrict__ out, int n) {
    int i = blockIdx.x * blockDim.x + threadIdx.x;
    if (i < n) out[i] = 0.f;
}

// One balanced wave: grid = 592 = 148 SMs x 4 CTAs. Each block owns a
// contiguous node range (<=128 nodes). Charges staged in SMEM once (single
// barrier). Main loop is barrier-free: 2 nodes/iter, front-batched float4
// LDG, per-element weight(reg) x charge(SMEM select) FMAs, interleaved warp
// shuffle reduce, then one atomicAdd per warp per node into pre-zeroed out.
__global__ void __launch_bounds__(256, 4)
energy_kernel(const float* __restrict__ nf,
              const float* __restrict__ ch,
              float* __restrict__ out, int n, int nblk) {
    __shared__ float cbuf[128 * 9];

    long base = (long)blockIdx.x * n / nblk;
    long end  = (long)(blockIdx.x + 1) * n / nblk;
    int cnt = (int)(end - base);
    if (cnt <= 0) return;

    int t = threadIdx.x;
    int lane = t & 31;

    // Per-thread element metadata (fixed):
    // slot A: float4 q = t        -> j = 4t+e            (x0 if t<64 else x1)
    // slot B: float4 q = t + 256  -> j = 1024 + 4t + e   (x2)
    // slot C: float4 q = t + 512  -> j = 2048 + 4t + e   (x2, t<64 only)
    float aA[4], aB[4], aC[4];
    int kA[4], kB[4], kC[4];
#pragma unroll
    for (int e = 0; e < 4; e++) {
        int jA = 4 * t + e;
        if (jA < 256) { aA[e] = g_w[jA]; kA[e] = 0; }
        else { int r = jA - 256; aA[e] = g_w[256 + r / 3]; kA[e] = 1 + r % 3; }
        int rB = 4 * t + e;
        aB[e] = g_w[512 + rB / 5]; kB[e] = 4 + rB % 5;
        int rC = 1024 + 4 * t + e;
        if (t < 64) { aC[e] = g_w[512 + rC / 5]; kC[e] = 4 + rC % 5; }
        else        { aC[e] = 0.f; kC[e] = 0; }
    }

    // Stage this block's charges once.
    {
        int total = cnt * 9;
        const float* cp = ch + base * 9;
        for (int i = t; i < total; i += 256) cbuf[i] = __ldg(cp + i);
    }
    __syncthreads();

    for (int loc = 0; loc < cnt; loc += 2) {
        long z0 = base + loc;
        bool v1 = (loc + 1) < cnt;

        const float4* p0 = (const float4*)(nf + z0 * 2304);
        const float4* p1 = p0 + 576;

        float4 Z = make_float4(0.f, 0.f, 0.f, 0.f);
        float4 A0 = p0[t], B0 = p0[256 + t];
        float4 C0 = Z, A1 = Z, B1 = Z, C1 = Z;
        if (t < 64) C0 = p0[512 + t];
        if (v1) {
            A1 = p1[t]; B1 = p1[256 + t];
            if (t < 64) C1 = p1[512 + t];
        }

        const float* cb0 = cbuf + 9 * loc;
        const float* cb1 = cb0 + 9;

        float acc0, acc1;
        if (t < 64) {
            acc0 = cb0[0] * (A0.x * aA[0] + A0.y * aA[1] + A0.z * aA[2] + A0.w * aA[3]);
            acc1 = cb1[0] * (A1.x * aA[0] + A1.y * aA[1] + A1.z * aA[2] + A1.w * aA[3]);
#pragma unroll
            for (int e = 0; e < 4; e++) {
                acc0 = fmaf((&C0.x)[e], aC[e] * cb0[kC[e]], acc0);
                acc1 = fmaf((&C1.x)[e], aC[e] * cb1[kC[e]], acc1);
            }
        } else {
            acc0 = 0.f; acc1 = 0.f;
#pragma unroll
            for (int e = 0; e < 4; e++) {
                acc0 = fmaf((&A0.x)[e], aA[e] * cb0[kA[e]], acc0);
                acc1 = fmaf((&A1.x)[e], aA[e] * cb1[kA[e]], acc1);
            }
        }
#pragma unroll
        for (int e = 0; e < 4; e++) {
            acc0 = fmaf((&B0.x)[e], aB[e] * cb0[kB[e]], acc0);
            acc1 = fmaf((&B1.x)[e], aB[e] * cb1[kB[e]], acc1);
        }

        // Interleaved warp reductions (two independent chains).
#pragma unroll
        for (int off = 16; off; off >>= 1) {
            acc0 += __shfl_xor_sync(0xffffffffu, acc0, off);
            acc1 += __shfl_xor_sync(0xffffffffu, acc1, off);
        }

        if (lane == 0) {
            atomicAdd(&out[z0], acc0);
            if (v1) atomicAdd(&out[z0 + 1], acc1);
        }
    }
}

extern "C" void kernel_launch(void* const* d_in, const int* in_sizes, int n_in,
                              void* d_out, int out_size) {
    const float* node_feats = (const float*)d_in[0];
    const float* charges    = (const float*)d_in[1];
    const float* W_lin0     = (const float*)d_in[2];
    const float* W_lin1     = (const float*)d_in[3];
    const float* W_lin2     = (const float*)d_in[4];
    const float* W_tp0      = (const float*)d_in[5];
    const float* W_tp1      = (const float*)d_in[6];
    const float* W_tp2      = (const float*)d_in[7];
    float* out = (float*)d_out;

    int n = in_sizes[1] / 9;   // number of nodes

    prep_weights_kernel<<<12, 256>>>(W_lin0, W_lin1, W_lin2, W_tp0, W_tp1, W_tp2);
    zero_out_kernel<<<(n + 255) / 256, 256>>>(out, n);

    // One balanced wave: 148 SMs x 4 CTAs/SM. Guarantee <=128 nodes/block.
    int nblk = 592;
    int minblk = (n + 127) / 128;
    if (minblk > nblk) nblk = minblk;
    energy_kernel<<<nblk, 256>>>(node_feats, charges, out, n, nblk);
}

// round 5
// speedup vs baseline: 1.2123x; 1.0638x over previous
#include <cuda_runtime.h>

// Effective weights: w_eff_m[u] = sum_v W_lin_m[u,v] * W_tp_m[v], pre-scaled.
// s0 = lin_norm*alpha = 1/(16*sqrt(768)); s1 = s0/sqrt(3); s2 = s0/sqrt(5)
__device__ float g_w[3 * 256];

#define S0 0.0022552744890219763f
#define S1 0.0013020833333333333f
#define S2 0.0010085837883053976f

// One warp per output row u (768 rows total): 96 blocks x 8 warps.
// Each lane loads 8 contiguous floats (2 x float4) of the row and of T,
// dot + shuffle reduce. Fully coalesced, deep MLP -> latency-bound ~2us.
__global__ void __launch_bounds__(256)
prep_weights_kernel(const float* __restrict__ W0,
                    const float* __restrict__ W1,
                    const float* __restrict__ W2,
                    const float* __restrict__ T0,
                    const float* __restrict__ T1,
                    const float* __restrict__ T2) {
    int gw = blockIdx.x * 8 + (threadIdx.x >> 5);   // global warp id = u index 0..767
    int lane = threadIdx.x & 31;
    int m = gw >> 8;
    int u = gw & 255;

    const float* W = (m == 0) ? W0 : (m == 1) ? W1 : W2;
    const float* T = (m == 0) ? T0 : (m == 1) ? T1 : T2;
    float scale = (m == 0) ? S0 : (m == 1) ? S1 : S2;

    const float4* row4 = (const float4*)(W + (size_t)u * 256) + lane * 2;
    const float4* t4   = (const float4*)T + lane * 2;

    float4 r0 = row4[0], r1 = row4[1];
    float4 w0 = t4[0],   w1 = t4[1];

    float acc = r0.x * w0.x + r0.y * w0.y + r0.z * w0.z + r0.w * w0.w
              + r1.x * w1.x + r1.y * w1.y + r1.z * w1.z + r1.w * w1.w;
#pragma unroll
    for (int off = 16; off; off >>= 1)
        acc += __shfl_xor_sync(0xffffffffu, acc, off);
    if (lane == 0) g_w[m * 256 + u] = acc * scale;
}

// One balanced wave: grid = 592 = 148 SMs x 4 CTAs. Each block owns a
// contiguous node range (<=128 nodes). Charges staged in SMEM once (single
// barrier). Main loop is barrier-free: 2 nodes/iter, front-batched float4
// streaming loads, per-element weight(reg) x charge(SMEM select) FMAs,
// interleaved warp shuffle reduce, one atomicAdd per warp per node into the
// memset-zeroed output.
__global__ void __launch_bounds__(256, 4)
energy_kernel(const float* __restrict__ nf,
              const float* __restrict__ ch,
              float* __restrict__ out, int n, int nblk) {
    __shared__ float cbuf[128 * 9];

    long base = (long)blockIdx.x * n / nblk;
    long end  = (long)(blockIdx.x + 1) * n / nblk;
    int cnt = (int)(end - base);
    if (cnt <= 0) return;

    int t = threadIdx.x;
    int lane = t & 31;

    // Per-thread element metadata (fixed):
    // slot A: float4 q = t        -> j = 4t+e            (x0 if t<64 else x1)
    // slot B: float4 q = t + 256  -> j = 1024 + 4t + e   (x2)
    // slot C: float4 q = t + 512  -> j = 2048 + 4t + e   (x2, t<64 only)
    float aA[4], aB[4], aC[4];
    int kA[4], kB[4], kC[4];
#pragma unroll
    for (int e = 0; e < 4; e++) {
        int jA = 4 * t + e;
        if (jA < 256) { aA[e] = g_w[jA]; kA[e] = 0; }
        else { int r = jA - 256; aA[e] = g_w[256 + r / 3]; kA[e] = 1 + r % 3; }
        int rB = 4 * t + e;
        aB[e] = g_w[512 + rB / 5]; kB[e] = 4 + rB % 5;
        int rC = 1024 + 4 * t + e;
        if (t < 64) { aC[e] = g_w[512 + rC / 5]; kC[e] = 4 + rC % 5; }
        else        { aC[e] = 0.f; kC[e] = 0; }
    }

    // Stage this block's charges once.
    {
        int total = cnt * 9;
        const float* cp = ch + base * 9;
        for (int i = t; i < total; i += 256) cbuf[i] = __ldg(cp + i);
    }
    __syncthreads();

    for (int loc = 0; loc < cnt; loc += 2) {
        long z0 = base + loc;
        bool v1 = (loc + 1) < cnt;

        const float4* p0 = (const float4*)(nf + z0 * 2304);
        const float4* p1 = p0 + 576;

        float4 Z = make_float4(0.f, 0.f, 0.f, 0.f);
        float4 A0 = __ldcs(p0 + t), B0 = __ldcs(p0 + 256 + t);
        float4 C0 = Z, A1 = Z, B1 = Z, C1 = Z;
        if (t < 64) C0 = __ldcs(p0 + 512 + t);
        if (v1) {
            A1 = __ldcs(p1 + t); B1 = __ldcs(p1 + 256 + t);
            if (t < 64) C1 = __ldcs(p1 + 512 + t);
        }

        const float* cb0 = cbuf + 9 * loc;
        const float* cb1 = cb0 + 9;

        float acc0, acc1;
        if (t < 64) {
            acc0 = cb0[0] * (A0.x * aA[0] + A0.y * aA[1] + A0.z * aA[2] + A0.w * aA[3]);
            acc1 = cb1[0] * (A1.x * aA[0] + A1.y * aA[1] + A1.z * aA[2] + A1.w * aA[3]);
#pragma unroll
            for (int e = 0; e < 4; e++) {
                acc0 = fmaf((&C0.x)[e], aC[e] * cb0[kC[e]], acc0);
                acc1 = fmaf((&C1.x)[e], aC[e] * cb1[kC[e]], acc1);
            }
        } else {
            acc0 = 0.f; acc1 = 0.f;
#pragma unroll
            for (int e = 0; e < 4; e++) {
                acc0 = fmaf((&A0.x)[e], aA[e] * cb0[kA[e]], acc0);
                acc1 = fmaf((&A1.x)[e], aA[e] * cb1[kA[e]], acc1);
            }
        }
#pragma unroll
        for (int e = 0; e < 4; e++) {
            acc0 = fmaf((&B0.x)[e], aB[e] * cb0[kB[e]], acc0);
            acc1 = fmaf((&B1.x)[e], aB[e] * cb1[kB[e]], acc1);
        }

        // Interleaved warp reductions (two independent chains).
#pragma unroll
        for (int off = 16; off; off >>= 1) {
            acc0 += __shfl_xor_sync(0xffffffffu, acc0, off);
            acc1 += __shfl_xor_sync(0xffffffffu, acc1, off);
        }

        if (lane == 0) {
            atomicAdd(&out[z0], acc0);
            if (v1) atomicAdd(&out[z0 + 1], acc1);
        }
    }
}

extern "C" void kernel_launch(void* const* d_in, const int* in_sizes, int n_in,
                              void* d_out, int out_size) {
    const float* node_feats = (const float*)d_in[0];
    const float* charges    = (const float*)d_in[1];
    const float* W_lin0     = (const float*)d_in[2];
    const float* W_lin1     = (const float*)d_in[3];
    const float* W_lin2     = (const float*)d_in[4];
    const float* W_tp0      = (const float*)d_in[5];
    const float* W_tp1      = (const float*)d_in[6];
    const float* W_tp2      = (const float*)d_in[7];
    float* out = (float*)d_out;

    int n = in_sizes[1] / 9;   // number of nodes

    cudaMemsetAsync(out, 0, (size_t)n * sizeof(float));
    prep_weights_kernel<<<96, 256>>>(W_lin0, W_lin1, W_lin2, W_tp0, W_tp1, W_tp2);

    // One balanced wave: 148 SMs x 4 CTAs/SM. Guarantee <=128 nodes/block.
    int nblk = 592;
    int minblk = (n + 127) / 128;
    if (minblk > nblk) nblk = minblk;
    energy_kernel<<<nblk, 256>>>(node_feats, charges, out, n, nblk);
}